// round 1
// baseline (speedup 1.0000x reference)
#include <cuda_runtime.h>
#include <cuda_fp16.h>
#include <cstdint>

#define T_TOK   4096
#define NEXP    8
#define DMODEL  1024
#define FFN     4096
#define NSLOTS  8192   // T * TOPK

// ---------------- scratch (device globals; no allocations allowed) ----------
__device__ __half g_xs[NSLOTS * DMODEL];                 // gathered x, fp16, expert-sorted
__device__ __half g_h[(size_t)NSLOTS * 2 * FFN];         // GEMM1 output (gate||up)
__device__ __half g_act[(size_t)NSLOTS * FFN];           // silu(gate)*up
__device__ int    g_cnt[NEXP];
__device__ int    g_off[NEXP];
__device__ int    g_sctr[NEXP];
__device__ int    g_slot_token[NSLOTS];
__device__ float  g_slot_coef[NSLOTS];
__device__ int    g_te[T_TOK * 2];
__device__ float  g_tw[T_TOK * 2];

// ---------------- small helpers --------------------------------------------
__device__ __forceinline__ uint32_t cvta_s(const void* p) {
    return (uint32_t)__cvta_generic_to_shared(p);
}
__device__ __forceinline__ void ldsm_x4(uint32_t* r, uint32_t a) {
    asm volatile("ldmatrix.sync.aligned.m8n8.x4.shared.b16 {%0,%1,%2,%3},[%4];\n"
                 : "=r"(r[0]), "=r"(r[1]), "=r"(r[2]), "=r"(r[3]) : "r"(a));
}
__device__ __forceinline__ void ldsm_x4_t(uint32_t* r, uint32_t a) {
    asm volatile("ldmatrix.sync.aligned.m8n8.x4.trans.shared.b16 {%0,%1,%2,%3},[%4];\n"
                 : "=r"(r[0]), "=r"(r[1]), "=r"(r[2]), "=r"(r[3]) : "r"(a));
}
__device__ __forceinline__ void mma_16816(float* c, const uint32_t* a, const uint32_t* b) {
    asm volatile("mma.sync.aligned.m16n8k16.row.col.f32.f16.f16.f32 "
                 "{%0,%1,%2,%3},{%4,%5,%6,%7},{%8,%9},{%0,%1,%2,%3};\n"
                 : "+f"(c[0]), "+f"(c[1]), "+f"(c[2]), "+f"(c[3])
                 : "r"(a[0]), "r"(a[1]), "r"(a[2]), "r"(a[3]), "r"(b[0]), "r"(b[1]));
}

// ---------------- tiny kernels ----------------------------------------------
__global__ void zero_kernel(float4* out, int n4) {
    int i = blockIdx.x * blockDim.x + threadIdx.x;
    if (i < n4) out[i] = make_float4(0.f, 0.f, 0.f, 0.f);
    if (blockIdx.x == 0 && threadIdx.x < NEXP) {
        g_cnt[threadIdx.x] = 0;
        g_sctr[threadIdx.x] = 0;
    }
}

__global__ void route_kernel(const float* __restrict__ gating) {
    int t = blockIdx.x * blockDim.x + threadIdx.x;
    if (t >= T_TOK) return;
    float p[NEXP];
    float m = -1e30f;
#pragma unroll
    for (int e = 0; e < NEXP; e++) { p[e] = gating[t * NEXP + e]; m = fmaxf(m, p[e]); }
#pragma unroll
    for (int e = 0; e < NEXP; e++) p[e] = __expf(p[e] - m);
    int i0 = 0;
#pragma unroll
    for (int e = 1; e < NEXP; e++) if (p[e] > p[i0]) i0 = e;
    int i1 = (i0 == 0) ? 1 : 0;
#pragma unroll
    for (int e = 0; e < NEXP; e++) if (e != i0 && p[e] > p[i1]) i1 = e;
    float w0 = p[i0], w1 = p[i1];
    float ws = w0 + w1;
    w0 /= ws; w1 /= ws;              // softmax denominator cancels exactly
    g_te[t * 2] = i0; g_te[t * 2 + 1] = i1;
    g_tw[t * 2] = w0; g_tw[t * 2 + 1] = w1;
    atomicAdd(&g_cnt[i0], 1);
    atomicAdd(&g_cnt[i1], 1);
}

__global__ void offsets_kernel() {
    if (threadIdx.x == 0 && blockIdx.x == 0) {
        int a = 0;
#pragma unroll
        for (int e = 0; e < NEXP; e++) { g_off[e] = a; a += g_cnt[e]; }
    }
}

__global__ void scatter_kernel() {
    int t = blockIdx.x * blockDim.x + threadIdx.x;
    if (t >= T_TOK) return;
#pragma unroll
    for (int k = 0; k < 2; k++) {
        int e = g_te[t * 2 + k];
        int p = g_off[e] + atomicAdd(&g_sctr[e], 1);
        g_slot_token[p] = t;
        g_slot_coef[p] = g_tw[t * 2 + k];
    }
}

__global__ void gather_x_kernel(const float* __restrict__ x) {
    unsigned i = blockIdx.x * blockDim.x + threadIdx.x;   // over NSLOTS * 512 float2
    if (i >= (unsigned)NSLOTS * (DMODEL / 2)) return;
    unsigned s = i >> 9;                                  // DMODEL/2 = 512
    unsigned c = i & 511;
    int t = g_slot_token[s];
    float2 v = ((const float2*)x)[(size_t)t * (DMODEL / 2) + c];
    ((__half2*)g_xs)[i] = __floats2half2_rn(v.x, v.y);
}

__global__ void swiglu_kernel() {
    unsigned i = blockIdx.x * blockDim.x + threadIdx.x;   // over NSLOTS * (FFN/2)
    if (i >= (unsigned)NSLOTS * (FFN / 2)) return;
    unsigned s = i >> 11;                                 // FFN/2 = 2048
    unsigned c = i & 2047;
    const __half2* hrow = (const __half2*)(g_h + (size_t)s * (2 * FFN));
    __half2 gh = hrow[c];
    __half2 uh = hrow[(FFN / 2) + c];
    float gx = __low2float(gh), gy = __high2float(gh);
    float ux = __low2float(uh), uy = __high2float(uh);
    float ax = gx / (1.f + __expf(-gx)) * ux;
    float ay = gy / (1.f + __expf(-gy)) * uy;
    ((__half2*)g_act)[i] = __floats2half2_rn(ax, ay);
}

// ---------------- fused dequant GEMM ----------------------------------------
// BM=128, BN=128, BK=32, 256 threads, mma.sync m16n8k16 fp16->fp32.
// MODE 0: A = g_xs  (K=1024), write h (N=8192)
// MODE 1: A = g_act (K=4096), epilogue coef * acc atomicAdd into out (N=1024)
#define APAD 40   // 32 + 8 halves
#define BPAD 136  // 128 + 8 halves

template <int MODE>
__global__ __launch_bounds__(256)
void moe_gemm(const int* __restrict__ Bq, const float* __restrict__ Bsc,
              float* __restrict__ Out, int K_TOTAL, int N_TOTAL) {
    const int e  = blockIdx.x >> 5;
    const int mt = blockIdx.x & 31;
    const int cntv = g_cnt[e];
    if (mt * 128 >= cntv) return;
    const int rows = min(128, cntv - mt * 128);
    const int row_base = g_off[e] + mt * 128;
    const int n0 = blockIdx.y * 128;
    const int tid = threadIdx.x;
    const int KT = K_TOTAL >> 5;   // BK = 32

    const __half* __restrict__ A = (MODE == 0) ? g_xs : g_act;

    __shared__ __half As[2 * 128 * APAD];
    __shared__ __half Bh[2 * 32 * BPAD];

    // ---- A loader: 2 cp.async(16B) per thread per tile --------------------
    auto load_A = [&](int stage, int kt) {
#pragma unroll
        for (int i = 0; i < 2; i++) {
            int chunk = tid + i * 256;       // 512 chunks: 128 rows x 4
            int r  = chunk >> 2;
            int cc = chunk & 3;
            int rr = (r < rows) ? r : 0;
            uint32_t dst = cvta_s(&As[(stage * 128 + r) * APAD + cc * 8]);
            const __half* src = A + (size_t)(row_base + rr) * K_TOTAL + kt * 32 + cc * 8;
            int sz = (r < rows) ? 16 : 0;
            asm volatile("cp.async.cg.shared.global [%0],[%1],16,%2;\n"
                         :: "r"(dst), "l"(src), "r"(sz));
        }
        asm volatile("cp.async.commit_group;\n");
    };

    // ---- B loader: 8 x int2 per thread, dequant to fp16 on STS ------------
    const int ncol = (tid & 63) * 2;         // 0..126
    const int rb   = tid >> 6;               // 0..3
    const size_t bq_base = (size_t)e * K_TOTAL * N_TOTAL + n0 + ncol;
    const size_t bs_base = (size_t)e * (K_TOTAL >> 7) * N_TOTAL + n0 + ncol;

    int2  creg[8];
    float s0 = 0.f, s1 = 0.f;
    auto load_B = [&](int kt) {
        const float* sp = Bsc + bs_base + (size_t)(kt >> 2) * N_TOTAL; // group = kt*32/128
        s0 = sp[0]; s1 = sp[1];
        const int* bp = Bq + bq_base + (size_t)(kt * 32 + rb) * N_TOTAL;
#pragma unroll
        for (int i = 0; i < 8; i++)
            creg[i] = *(const int2*)(bp + (size_t)(i * 4) * N_TOTAL);
    };
    auto store_B = [&](int stage) {
#pragma unroll
        for (int i = 0; i < 8; i++) {
            __half2 v = __halves2half2(__float2half_rn((float)(creg[i].x - 8) * s0),
                                       __float2half_rn((float)(creg[i].y - 8) * s1));
            *(__half2*)&Bh[(stage * 32 + rb + i * 4) * BPAD + ncol] = v;
        }
    };

    float acc[4][4][4];
#pragma unroll
    for (int a = 0; a < 4; a++)
#pragma unroll
        for (int b = 0; b < 4; b++)
#pragma unroll
            for (int c = 0; c < 4; c++) acc[a][b][c] = 0.f;

    const int lane = tid & 31;
    const int wid  = tid >> 5;
    const int wm = (wid >> 2) * 64;
    const int wn = (wid & 3) * 32;
    const int lr = lane & 15;
    const int lc = lane >> 4;

    // prologue
    load_A(0, 0);
    load_B(0);
    asm volatile("cp.async.wait_group 0;\n");
    store_B(0);
    __syncthreads();

    for (int kt = 0; kt < KT; kt++) {
        int cur = kt & 1, nxt = cur ^ 1;
        if (kt + 1 < KT) { load_A(nxt, kt + 1); load_B(kt + 1); }

        const __half* Ab = &As[cur * 128 * APAD];
        const __half* Bb = &Bh[cur * 32 * BPAD];
#pragma unroll
        for (int kk = 0; kk < 2; kk++) {       // two k16 steps
            uint32_t af[4][4];
#pragma unroll
            for (int mi = 0; mi < 4; mi++)
                ldsm_x4(af[mi], cvta_s(&Ab[(wm + mi * 16 + lr) * APAD + kk * 16 + lc * 8]));
            uint32_t bf[4][2];
#pragma unroll
            for (int nj = 0; nj < 2; nj++) {
                uint32_t t[4];
                ldsm_x4_t(t, cvta_s(&Bb[(kk * 16 + lr) * BPAD + wn + nj * 16 + lc * 8]));
                bf[nj * 2][0] = t[0]; bf[nj * 2][1] = t[1];
                bf[nj * 2 + 1][0] = t[2]; bf[nj * 2 + 1][1] = t[3];
            }
#pragma unroll
            for (int mi = 0; mi < 4; mi++)
#pragma unroll
                for (int ni = 0; ni < 4; ni++)
                    mma_16816(acc[mi][ni], af[mi], bf[ni]);
        }
        if (kt + 1 < KT) {
            store_B(nxt);
            asm volatile("cp.async.wait_group 0;\n");
            __syncthreads();
        }
    }

    // ---- epilogue ----------------------------------------------------------
    if (MODE == 0) {
#pragma unroll
        for (int mi = 0; mi < 4; mi++) {
            int r0 = wm + mi * 16 + (lane >> 2);
            int r1 = r0 + 8;
#pragma unroll
            for (int ni = 0; ni < 4; ni++) {
                int col = n0 + wn + ni * 8 + (lane & 3) * 2;
                if (r0 < rows)
                    *(__half2*)&g_h[(size_t)(row_base + r0) * (2 * FFN) + col] =
                        __floats2half2_rn(acc[mi][ni][0], acc[mi][ni][1]);
                if (r1 < rows)
                    *(__half2*)&g_h[(size_t)(row_base + r1) * (2 * FFN) + col] =
                        __floats2half2_rn(acc[mi][ni][2], acc[mi][ni][3]);
            }
        }
    } else {
#pragma unroll
        for (int mi = 0; mi < 4; mi++) {
            int r0 = wm + mi * 16 + (lane >> 2);
            int r1 = r0 + 8;
            int tok0 = 0, tok1 = 0;
            float cf0 = 0.f, cf1 = 0.f;
            if (r0 < rows) { int s = row_base + r0; tok0 = g_slot_token[s]; cf0 = g_slot_coef[s]; }
            if (r1 < rows) { int s = row_base + r1; tok1 = g_slot_token[s]; cf1 = g_slot_coef[s]; }
#pragma unroll
            for (int ni = 0; ni < 4; ni++) {
                int col = n0 + wn + ni * 8 + (lane & 3) * 2;
                if (r0 < rows) {
                    atomicAdd(&Out[(size_t)tok0 * DMODEL + col],     cf0 * acc[mi][ni][0]);
                    atomicAdd(&Out[(size_t)tok0 * DMODEL + col + 1], cf0 * acc[mi][ni][1]);
                }
                if (r1 < rows) {
                    atomicAdd(&Out[(size_t)tok1 * DMODEL + col],     cf1 * acc[mi][ni][2]);
                    atomicAdd(&Out[(size_t)tok1 * DMODEL + col + 1], cf1 * acc[mi][ni][3]);
                }
            }
        }
    }
}

// ---------------- launch -----------------------------------------------------
extern "C" void kernel_launch(void* const* d_in, const int* in_sizes, int n_in,
                              void* d_out, int out_size) {
    const float* x      = (const float*)d_in[0];
    const float* gating = (const float*)d_in[1];
    const int*   w1q    = (const int*)d_in[2];
    const int*   w2q    = (const int*)d_in[3];
    const float* w1s    = (const float*)d_in[4];
    const float* w2s    = (const float*)d_in[5];
    float* out = (float*)d_out;

    int n4 = out_size / 4;
    zero_kernel<<<(n4 + 255) / 256, 256>>>((float4*)out, n4);
    route_kernel<<<(T_TOK + 255) / 256, 256>>>(gating);
    offsets_kernel<<<1, 32>>>();
    scatter_kernel<<<(T_TOK + 255) / 256, 256>>>();
    gather_x_kernel<<<(NSLOTS * (DMODEL / 2) + 255) / 256, 256>>>(x);

    // GEMM1: x[slots,1024] @ dequant(w1[e])[1024,8192] -> h
    dim3 g1(256, (2 * FFN) / 128);
    moe_gemm<0><<<g1, 256>>>(w1q, w1s, nullptr, DMODEL, 2 * FFN);

    swiglu_kernel<<<(NSLOTS * (FFN / 2) + 255) / 256, 256>>>();

    // GEMM2: act[slots,4096] @ dequant(w2[e])[4096,1024] -> +=coef -> out
    dim3 g2(256, DMODEL / 128);
    moe_gemm<1><<<g2, 256>>>(w2q, w2s, out, FFN, DMODEL);
}

// round 3
// speedup vs baseline: 1.0022x; 1.0022x over previous
#include <cuda_runtime.h>
#include <cuda_fp16.h>
#include <cstdint>

#define T_TOK   4096
#define NEXP    8
#define DMODEL  1024
#define FFN     4096
#define NSLOTS  8192   // T * TOPK

// ---------------- scratch (device globals; no allocations allowed) ----------
__device__ __half g_xs[NSLOTS * DMODEL];                 // gathered x, fp16, expert-sorted
__device__ __half g_h[(size_t)NSLOTS * 2 * FFN];         // GEMM1 output (gate||up)
__device__ __half g_act[(size_t)NSLOTS * FFN];           // silu(gate)*up
__device__ int    g_cnt[NEXP];
__device__ int    g_off[NEXP];
__device__ int    g_sctr[NEXP];
__device__ int    g_slot_token[NSLOTS];
__device__ float  g_slot_coef[NSLOTS];
__device__ int    g_te[T_TOK * 2];
__device__ float  g_tw[T_TOK * 2];

// ---------------- small helpers --------------------------------------------
__device__ __forceinline__ uint32_t cvta_s(const void* p) {
    return (uint32_t)__cvta_generic_to_shared(p);
}
__device__ __forceinline__ void ldsm_x4(uint32_t* r, uint32_t a) {
    asm volatile("ldmatrix.sync.aligned.m8n8.x4.shared.b16 {%0,%1,%2,%3},[%4];\n"
                 : "=r"(r[0]), "=r"(r[1]), "=r"(r[2]), "=r"(r[3]) : "r"(a));
}
__device__ __forceinline__ void ldsm_x4_t(uint32_t* r, uint32_t a) {
    asm volatile("ldmatrix.sync.aligned.m8n8.x4.trans.shared.b16 {%0,%1,%2,%3},[%4];\n"
                 : "=r"(r[0]), "=r"(r[1]), "=r"(r[2]), "=r"(r[3]) : "r"(a));
}
__device__ __forceinline__ void mma_16816(float* c, const uint32_t* a, const uint32_t* b) {
    asm volatile("mma.sync.aligned.m16n8k16.row.col.f32.f16.f16.f32 "
                 "{%0,%1,%2,%3},{%4,%5,%6,%7},{%8,%9},{%0,%1,%2,%3};\n"
                 : "+f"(c[0]), "+f"(c[1]), "+f"(c[2]), "+f"(c[3])
                 : "r"(a[0]), "r"(a[1]), "r"(a[2]), "r"(a[3]), "r"(b[0]), "r"(b[1]));
}

// ---------------- tiny kernels ----------------------------------------------
__global__ void zero_kernel(float4* out, int n4) {
    int i = blockIdx.x * blockDim.x + threadIdx.x;
    if (i < n4) out[i] = make_float4(0.f, 0.f, 0.f, 0.f);
    if (blockIdx.x == 0 && threadIdx.x < NEXP) {
        g_cnt[threadIdx.x] = 0;
        g_sctr[threadIdx.x] = 0;
    }
}

__global__ void route_kernel(const float* __restrict__ gating) {
    int t = blockIdx.x * blockDim.x + threadIdx.x;
    if (t >= T_TOK) return;
    float p[NEXP];
    float m = -1e30f;
#pragma unroll
    for (int e = 0; e < NEXP; e++) { p[e] = gating[t * NEXP + e]; m = fmaxf(m, p[e]); }
#pragma unroll
    for (int e = 0; e < NEXP; e++) p[e] = __expf(p[e] - m);
    int i0 = 0;
#pragma unroll
    for (int e = 1; e < NEXP; e++) if (p[e] > p[i0]) i0 = e;
    int i1 = (i0 == 0) ? 1 : 0;
#pragma unroll
    for (int e = 0; e < NEXP; e++) if (e != i0 && p[e] > p[i1]) i1 = e;
    float w0 = p[i0], w1 = p[i1];
    float ws = w0 + w1;
    w0 /= ws; w1 /= ws;              // softmax denominator cancels exactly
    g_te[t * 2] = i0; g_te[t * 2 + 1] = i1;
    g_tw[t * 2] = w0; g_tw[t * 2 + 1] = w1;
    atomicAdd(&g_cnt[i0], 1);
    atomicAdd(&g_cnt[i1], 1);
}

__global__ void offsets_kernel() {
    if (threadIdx.x == 0 && blockIdx.x == 0) {
        int a = 0;
#pragma unroll
        for (int e = 0; e < NEXP; e++) { g_off[e] = a; a += g_cnt[e]; }
    }
}

__global__ void scatter_kernel() {
    int t = blockIdx.x * blockDim.x + threadIdx.x;
    if (t >= T_TOK) return;
#pragma unroll
    for (int k = 0; k < 2; k++) {
        int e = g_te[t * 2 + k];
        int p = g_off[e] + atomicAdd(&g_sctr[e], 1);
        g_slot_token[p] = t;
        g_slot_coef[p] = g_tw[t * 2 + k];
    }
}

__global__ void gather_x_kernel(const float* __restrict__ x) {
    unsigned i = blockIdx.x * blockDim.x + threadIdx.x;   // over NSLOTS * 512 float2
    if (i >= (unsigned)NSLOTS * (DMODEL / 2)) return;
    unsigned s = i >> 9;                                  // DMODEL/2 = 512
    unsigned c = i & 511;
    int t = g_slot_token[s];
    float2 v = ((const float2*)x)[(size_t)t * (DMODEL / 2) + c];
    ((__half2*)g_xs)[i] = __floats2half2_rn(v.x, v.y);
}

__global__ void swiglu_kernel() {
    unsigned i = blockIdx.x * blockDim.x + threadIdx.x;   // over NSLOTS * (FFN/2)
    if (i >= (unsigned)NSLOTS * (FFN / 2)) return;
    unsigned s = i >> 11;                                 // FFN/2 = 2048
    unsigned c = i & 2047;
    const __half2* hrow = (const __half2*)(g_h + (size_t)s * (2 * FFN));
    __half2 gh = hrow[c];
    __half2 uh = hrow[(FFN / 2) + c];
    float gx = __low2float(gh), gy = __high2float(gh);
    float ux = __low2float(uh), uy = __high2float(uh);
    float ax = gx / (1.f + __expf(-gx)) * ux;
    float ay = gy / (1.f + __expf(-gy)) * uy;
    ((__half2*)g_act)[i] = __floats2half2_rn(ax, ay);
}

// ---------------- fused dequant GEMM ----------------------------------------
// BM=128, BN=128, BK=32, 256 threads, mma.sync m16n8k16 fp16->fp32.
// MODE 0: A = g_xs  (K=1024), write h (N=8192)
// MODE 1: A = g_act (K=4096), epilogue coef * acc atomicAdd into out (N=1024)
#define APAD 40   // 32 + 8 halves
#define BPAD 136  // 128 + 8 halves

template <int MODE>
__global__ __launch_bounds__(256)
void moe_gemm(const int* __restrict__ Bq, const float* __restrict__ Bsc,
              float* __restrict__ Out, int K_TOTAL, int N_TOTAL) {
    const int e  = blockIdx.x >> 5;
    const int mt = blockIdx.x & 31;
    const int cntv = g_cnt[e];
    if (mt * 128 >= cntv) return;
    const int rows = min(128, cntv - mt * 128);
    const int row_base = g_off[e] + mt * 128;
    const int n0 = blockIdx.y * 128;
    const int tid = threadIdx.x;
    const int KT = K_TOTAL >> 5;   // BK = 32

    const __half* __restrict__ A = (MODE == 0) ? g_xs : g_act;

    __shared__ __half As[2 * 128 * APAD];
    __shared__ __half Bh[2 * 32 * BPAD];

    // ---- A loader: 2 cp.async(16B) per thread per tile --------------------
    auto load_A = [&](int stage, int kt) {
#pragma unroll
        for (int i = 0; i < 2; i++) {
            int chunk = tid + i * 256;       // 512 chunks: 128 rows x 4
            int r  = chunk >> 2;
            int cc = chunk & 3;
            int rr = (r < rows) ? r : 0;
            uint32_t dst = cvta_s(&As[(stage * 128 + r) * APAD + cc * 8]);
            const __half* src = A + (size_t)(row_base + rr) * K_TOTAL + kt * 32 + cc * 8;
            int sz = (r < rows) ? 16 : 0;
            asm volatile("cp.async.cg.shared.global [%0],[%1],16,%2;\n"
                         :: "r"(dst), "l"(src), "r"(sz));
        }
        asm volatile("cp.async.commit_group;\n");
    };

    // ---- B loader: 8 x int2 per thread, dequant to fp16 on STS ------------
    const int ncol = (tid & 63) * 2;         // 0..126
    const int rb   = tid >> 6;               // 0..3
    const size_t bq_base = (size_t)e * K_TOTAL * N_TOTAL + n0 + ncol;
    const size_t bs_base = (size_t)e * (K_TOTAL >> 7) * N_TOTAL + n0 + ncol;

    int2  creg[8];
    float s0 = 0.f, s1 = 0.f;
    auto load_B = [&](int kt) {
        const float* sp = Bsc + bs_base + (size_t)(kt >> 2) * N_TOTAL; // group = kt*32/128
        s0 = sp[0]; s1 = sp[1];
        const int* bp = Bq + bq_base + (size_t)(kt * 32 + rb) * N_TOTAL;
#pragma unroll
        for (int i = 0; i < 8; i++)
            creg[i] = *(const int2*)(bp + (size_t)(i * 4) * N_TOTAL);
    };
    auto store_B = [&](int stage) {
#pragma unroll
        for (int i = 0; i < 8; i++) {
            __half2 v = __halves2half2(__float2half_rn((float)(creg[i].x - 8) * s0),
                                       __float2half_rn((float)(creg[i].y - 8) * s1));
            *(__half2*)&Bh[(stage * 32 + rb + i * 4) * BPAD + ncol] = v;
        }
    };

    float acc[4][4][4];
#pragma unroll
    for (int a = 0; a < 4; a++)
#pragma unroll
        for (int b = 0; b < 4; b++)
#pragma unroll
            for (int c = 0; c < 4; c++) acc[a][b][c] = 0.f;

    const int lane = tid & 31;
    const int wid  = tid >> 5;
    const int wm = (wid >> 2) * 64;
    const int wn = (wid & 3) * 32;
    const int lr = lane & 15;
    const int lc = lane >> 4;

    // prologue
    load_A(0, 0);
    load_B(0);
    asm volatile("cp.async.wait_group 0;\n");
    store_B(0);
    __syncthreads();

    for (int kt = 0; kt < KT; kt++) {
        int cur = kt & 1, nxt = cur ^ 1;
        if (kt + 1 < KT) { load_A(nxt, kt + 1); load_B(kt + 1); }

        const __half* Ab = &As[cur * 128 * APAD];
        const __half* Bb = &Bh[cur * 32 * BPAD];
#pragma unroll
        for (int kk = 0; kk < 2; kk++) {       // two k16 steps
            uint32_t af[4][4];
#pragma unroll
            for (int mi = 0; mi < 4; mi++)
                ldsm_x4(af[mi], cvta_s(&Ab[(wm + mi * 16 + lr) * APAD + kk * 16 + lc * 8]));
            uint32_t bf[4][2];
#pragma unroll
            for (int nj = 0; nj < 2; nj++) {
                uint32_t t[4];
                ldsm_x4_t(t, cvta_s(&Bb[(kk * 16 + lr) * BPAD + wn + nj * 16 + lc * 8]));
                bf[nj * 2][0] = t[0]; bf[nj * 2][1] = t[1];
                bf[nj * 2 + 1][0] = t[2]; bf[nj * 2 + 1][1] = t[3];
            }
#pragma unroll
            for (int mi = 0; mi < 4; mi++)
#pragma unroll
                for (int ni = 0; ni < 4; ni++)
                    mma_16816(acc[mi][ni], af[mi], bf[ni]);
        }
        if (kt + 1 < KT) {
            store_B(nxt);
            asm volatile("cp.async.wait_group 0;\n");
            __syncthreads();
        }
    }

    // ---- epilogue ----------------------------------------------------------
    if (MODE == 0) {
#pragma unroll
        for (int mi = 0; mi < 4; mi++) {
            int r0 = wm + mi * 16 + (lane >> 2);
            int r1 = r0 + 8;
#pragma unroll
            for (int ni = 0; ni < 4; ni++) {
                int col = n0 + wn + ni * 8 + (lane & 3) * 2;
                if (r0 < rows)
                    *(__half2*)&g_h[(size_t)(row_base + r0) * (2 * FFN) + col] =
                        __floats2half2_rn(acc[mi][ni][0], acc[mi][ni][1]);
                if (r1 < rows)
                    *(__half2*)&g_h[(size_t)(row_base + r1) * (2 * FFN) + col] =
                        __floats2half2_rn(acc[mi][ni][2], acc[mi][ni][3]);
            }
        }
    } else {
#pragma unroll
        for (int mi = 0; mi < 4; mi++) {
            int r0 = wm + mi * 16 + (lane >> 2);
            int r1 = r0 + 8;
            int tok0 = 0, tok1 = 0;
            float cf0 = 0.f, cf1 = 0.f;
            if (r0 < rows) { int s = row_base + r0; tok0 = g_slot_token[s]; cf0 = g_slot_coef[s]; }
            if (r1 < rows) { int s = row_base + r1; tok1 = g_slot_token[s]; cf1 = g_slot_coef[s]; }
#pragma unroll
            for (int ni = 0; ni < 4; ni++) {
                int col = n0 + wn + ni * 8 + (lane & 3) * 2;
                if (r0 < rows) {
                    atomicAdd(&Out[(size_t)tok0 * DMODEL + col],     cf0 * acc[mi][ni][0]);
                    atomicAdd(&Out[(size_t)tok0 * DMODEL + col + 1], cf0 * acc[mi][ni][1]);
                }
                if (r1 < rows) {
                    atomicAdd(&Out[(size_t)tok1 * DMODEL + col],     cf1 * acc[mi][ni][2]);
                    atomicAdd(&Out[(size_t)tok1 * DMODEL + col + 1], cf1 * acc[mi][ni][3]);
                }
            }
        }
    }
}

// ---------------- launch -----------------------------------------------------
extern "C" void kernel_launch(void* const* d_in, const int* in_sizes, int n_in,
                              void* d_out, int out_size) {
    const float* x      = (const float*)d_in[0];
    const float* gating = (const float*)d_in[1];
    const int*   w1q    = (const int*)d_in[2];
    const int*   w2q    = (const int*)d_in[3];
    const float* w1s    = (const float*)d_in[4];
    const float* w2s    = (const float*)d_in[5];
    float* out = (float*)d_out;

    int n4 = out_size / 4;
    zero_kernel<<<(n4 + 255) / 256, 256>>>((float4*)out, n4);
    route_kernel<<<(T_TOK + 255) / 256, 256>>>(gating);
    offsets_kernel<<<1, 32>>>();
    scatter_kernel<<<(T_TOK + 255) / 256, 256>>>();
    gather_x_kernel<<<(NSLOTS * (DMODEL / 2) + 255) / 256, 256>>>(x);

    // GEMM1: x[slots,1024] @ dequant(w1[e])[1024,8192] -> h
    dim3 g1(256, (2 * FFN) / 128);
    moe_gemm<0><<<g1, 256>>>(w1q, w1s, nullptr, DMODEL, 2 * FFN);

    swiglu_kernel<<<(NSLOTS * (FFN / 2) + 255) / 256, 256>>>();

    // GEMM2: act[slots,4096] @ dequant(w2[e])[4096,1024] -> +=coef -> out
    dim3 g2(256, DMODEL / 128);
    moe_gemm<1><<<g2, 256>>>(w2q, w2s, out, FFN, DMODEL);
}